// round 15
// baseline (speedup 1.0000x reference)
#include <cuda_runtime.h>

#define D 64
#define NMAX 100032
#define BM 96

// ---------------- device scratch (no allocations allowed) ----------------
__device__ __align__(16) float g_tmp[NMAX * D];   // act(h) + neighbor sums (GEMM1 input)
__device__ __align__(16) float g_act[NMAX * D];   // read-only act(h) for edge gather
__device__ __align__(16) float g_u[NMAX * D];     // GEMM1 output (pre inner-BN)
__device__ __align__(16) float g_v[NMAX * D];     // GEMM2 output (pre outer-BN)
__device__ double g_sumA[D], g_sqA[D], g_sumB[D], g_sqB[D];
__device__ __align__(16) float g_scA[D], g_shA[D];   // inner BN scale/shift
__device__ __align__(16) float g_scB[D], g_shB[D];   // outer BN scale/shift

// ---------------- f32x2 helpers ----------------
__device__ __forceinline__ unsigned long long pack2(float x) {
    unsigned long long r;
    asm("mov.b64 %0, {%1, %1};" : "=l"(r) : "r"(__float_as_uint(x)));
    return r;
}
__device__ __forceinline__ void ffma2(unsigned long long& d,
                                      unsigned long long a, unsigned long long b) {
    asm("fma.rn.f32x2 %0, %1, %2, %0;" : "+l"(d) : "l"(a), "l"(b));
}
union Cvt2 { unsigned long long u; float2 f; };

// apply outer-BN(+ReLU) of the previous layer when reading h
__device__ __forceinline__ float4 act_prev(float4 a, int q4, int use_v) {
    if (use_v) {
        float4 s = *(const float4*)&g_scB[q4];
        float4 t = *(const float4*)&g_shB[q4];
        a.x = fmaxf(fmaf(a.x, s.x, t.x), 0.f);
        a.y = fmaxf(fmaf(a.y, s.y, t.y), 0.f);
        a.z = fmaxf(fmaf(a.z, s.z, t.z), 0.f);
        a.w = fmaxf(fmaf(a.w, s.w, t.w), 0.f);
    }
    return a;
}

// ---------------- tmp = act(h) (+ g_act copy for layers>=1); zero inner-BN accumulators ----------------
__global__ void init_tmp_kernel(const float* __restrict__ x, int use_v, int n) {
    int idx = blockIdx.x * blockDim.x + threadIdx.x;
    if (blockIdx.x == 0 && threadIdx.x < D) {
        g_sumA[threadIdx.x] = 0.0;
        g_sqA[threadIdx.x] = 0.0;
    }
    if (idx >= n * 16) return;
    int q4 = (idx & 15) * 4;
    const float* h = use_v ? g_v : x;
    float4 a = __ldg((const float4*)(h) + idx);
    a = act_prev(a, q4, use_v);
    *((float4*)g_tmp + idx) = a;
    if (use_v) *((float4*)g_act + idx) = a;   // layer 0: edge reads x directly
}

// ---------------- tmp[dst] += act_src[src]; 8 lanes/edge x 8 channels/lane ----------------
__global__ void edge_kernel(const float* __restrict__ act_src,
                            const int* __restrict__ ei, int E) {
    int idx = blockIdx.x * blockDim.x + threadIdx.x;
    if (idx >= E * 8) return;
    int e = idx >> 3;
    int q8 = (idx & 7) * 8;
    int s = __ldg(&ei[e]);
    int d = __ldg(&ei[E + e]);
    const float* src = act_src + (size_t)s * D + q8;
    float* dst = g_tmp + (size_t)d * D + q8;
    float4 a0 = __ldg((const float4*)src);
    float4 a1 = __ldg((const float4*)(src + 4));
    atomicAdd((float4*)dst, a0);
    atomicAdd((float4*)(dst + 4), a1);
}

// ---------------- fused GEMM + bias + BN-stat accumulation (FFMA2 core, R9 layout) ----------------
// which==0: u = tmp @ W + b,               stats -> sumA/sqA
// which==1: v = relu(bn_inner(u)) @ W + b, stats -> sumB/sqB
__global__ __launch_bounds__(256) void gemm_bn_kernel(
    const float* __restrict__ Wall, const float* __restrict__ ball,
    int l, int which, int n)
{
    __shared__ float As[BM][68];      // padded, float4-aligned
    __shared__ float Ws[D][D];
    __shared__ float red[16][D];

    const float* W = Wall + (size_t)l * D * D;
    const float* bias = ball + (size_t)l * D;
    const float* A = which ? g_u : g_tmp;
    float* out = which ? g_v : g_u;
    double* sum = which ? g_sumB : g_sumA;
    double* sq  = which ? g_sqB  : g_sqA;

    int tid = threadIdx.x;
    int row0 = blockIdx.x * BM;

    // load W tile (64x64)
    #pragma unroll
    for (int i = tid; i < D * D / 4; i += 256)
        ((float4*)Ws)[i] = __ldg((const float4*)W + i);

    // load A tile (BM x 64), applying inner BN + ReLU for GEMM2
    for (int i = tid; i < BM * 16; i += 256) {
        int r = i >> 4, k4 = (i & 15) * 4;
        int gr = row0 + r;
        float4 av = make_float4(0.f, 0.f, 0.f, 0.f);
        if (gr < n) av = __ldg((const float4*)(A + (size_t)gr * D + k4));
        if (which) {
            float4 s = *(const float4*)&g_scA[k4];
            float4 t = *(const float4*)&g_shA[k4];
            av.x = fmaxf(fmaf(av.x, s.x, t.x), 0.f);
            av.y = fmaxf(fmaf(av.y, s.y, t.y), 0.f);
            av.z = fmaxf(fmaf(av.z, s.z, t.z), 0.f);
            av.w = fmaxf(fmaf(av.w, s.w, t.w), 0.f);
        }
        *(float4*)&As[r][k4] = av;
    }
    __syncthreads();

    int tx = tid & 15, ty = tid >> 4;
    int c0 = tx * 4;
    unsigned long long acc01[6], acc23[6];
    #pragma unroll
    for (int i = 0; i < 6; i++) { acc01[i] = 0ull; acc23[i] = 0ull; }

    #pragma unroll
    for (int k = 0; k < D; k += 4) {
        ulonglong2 w0 = *(const ulonglong2*)&Ws[k + 0][c0];
        ulonglong2 w1 = *(const ulonglong2*)&Ws[k + 1][c0];
        ulonglong2 w2 = *(const ulonglong2*)&Ws[k + 2][c0];
        ulonglong2 w3 = *(const ulonglong2*)&Ws[k + 3][c0];
        #pragma unroll
        for (int i = 0; i < 6; i++) {
            float4 a = *(const float4*)&As[ty * 6 + i][k];
            unsigned long long px = pack2(a.x), py = pack2(a.y);
            unsigned long long pz = pack2(a.z), pw = pack2(a.w);
            ffma2(acc01[i], px, w0.x); ffma2(acc23[i], px, w0.y);
            ffma2(acc01[i], py, w1.x); ffma2(acc23[i], py, w1.y);
            ffma2(acc01[i], pz, w2.x); ffma2(acc23[i], pz, w2.y);
            ffma2(acc01[i], pw, w3.x); ffma2(acc23[i], pw, w3.y);
        }
    }

    float4 bv = *(const float4*)(bias + c0);
    float csum[4] = {0.f, 0.f, 0.f, 0.f};
    float csq[4]  = {0.f, 0.f, 0.f, 0.f};
    #pragma unroll
    for (int i = 0; i < 6; i++) {
        int gr = row0 + ty * 6 + i;
        if (gr < n) {
            Cvt2 c01, c23; c01.u = acc01[i]; c23.u = acc23[i];
            float4 o;
            o.x = c01.f.x + bv.x;
            o.y = c01.f.y + bv.y;
            o.z = c23.f.x + bv.z;
            o.w = c23.f.y + bv.w;
            *(float4*)(out + (size_t)gr * D + c0) = o;
            csum[0] += o.x; csq[0] += o.x * o.x;
            csum[1] += o.y; csq[1] += o.y * o.y;
            csum[2] += o.z; csq[2] += o.z * o.z;
            csum[3] += o.w; csq[3] += o.w * o.w;
        }
    }
    __syncthreads();
    #pragma unroll
    for (int c = 0; c < 4; c++) red[ty][c0 + c] = csum[c];
    __syncthreads();
    if (tid < D) {
        float s = 0.f;
        #pragma unroll
        for (int t = 0; t < 16; t++) s += red[t][tid];
        atomicAdd(&sum[tid], (double)s);
    }
    __syncthreads();
    #pragma unroll
    for (int c = 0; c < 4; c++) red[ty][c0 + c] = csq[c];
    __syncthreads();
    if (tid < D) {
        float s = 0.f;
        #pragma unroll
        for (int t = 0; t < 16; t++) s += red[t][tid];
        atomicAdd(&sq[tid], (double)s);
    }
}

// ---------------- finalize BN stats into scale/shift ----------------
__global__ void stats_kernel(const float* __restrict__ gamma,
                             const float* __restrict__ beta,
                             int which, double inv_n) {
    int c = threadIdx.x;
    double s, q;
    if (which == 0) { s = g_sumA[c]; q = g_sqA[c]; }
    else            { s = g_sumB[c]; q = g_sqB[c]; }
    float mean = (float)(s * inv_n);
    float var  = (float)(q * inv_n - (s * inv_n) * (s * inv_n));
    float sc = gamma[c] * rsqrtf(var + 1e-5f);
    float sh = beta[c] - mean * sc;
    if (which == 0) {
        g_scA[c] = sc; g_shA[c] = sh;
        g_sumB[c] = 0.0; g_sqB[c] = 0.0;   // zero outer-BN accumulators for GEMM2
    } else {
        g_scB[c] = sc; g_shB[c] = sh;
    }
}

// ---------------- write node_representation + node_select ----------------
__global__ void finalize_kernel(const int* __restrict__ bi,
                                float* __restrict__ out, int n, int K) {
    int idx = blockIdx.x * blockDim.x + threadIdx.x;
    int total = (n + K) * 16;
    if (idx >= total) return;
    int q4 = (idx & 15) * 4;
    int item = idx >> 4;
    int row;
    size_t opos;
    if (item < n) { row = item; opos = (size_t)item * D + q4; }
    else {
        int k = item - n;
        row = __ldg(&bi[k]);
        opos = (size_t)n * D + (size_t)k * D + q4;
    }
    float4 a = *(const float4*)&g_v[(size_t)row * D + q4];
    float4 s = *(const float4*)&g_scB[q4];
    float4 t = *(const float4*)&g_shB[q4];
    float4 o;
    o.x = fmaf(a.x, s.x, t.x);
    o.y = fmaf(a.y, s.y, t.y);
    o.z = fmaf(a.z, s.z, t.z);
    o.w = fmaf(a.w, s.w, t.w);
    *(float4*)&out[opos] = o;
}

extern "C" void kernel_launch(void* const* d_in, const int* in_sizes, int n_in,
                              void* d_out, int out_size) {
    const float* x   = (const float*)d_in[0];
    const int*   ei  = (const int*)d_in[1];
    const int*   bi  = (const int*)d_in[2];
    const float* W1  = (const float*)d_in[3];
    const float* b1  = (const float*)d_in[4];
    const float* g1  = (const float*)d_in[5];
    const float* be1 = (const float*)d_in[6];
    const float* W2  = (const float*)d_in[7];
    const float* b2  = (const float*)d_in[8];
    const float* g2  = (const float*)d_in[9];
    const float* be2 = (const float*)d_in[10];
    float* out = (float*)d_out;

    int n = in_sizes[0] / D;
    int E = in_sizes[1] / 2;
    int K = in_sizes[2];
    int L = in_sizes[3] / (D * D);

    int gInit = (n * 16 + 255) / 256;
    int gEdge = (E * 8 + 255) / 256;
    int gGemm = (n + BM - 1) / BM;
    int gFin  = ((n + K) * 16 + 255) / 256;
    double inv_n = 1.0 / (double)n;

    // device pointer to g_act for the edge kernel on layers >= 1
    float* act_dev = nullptr;
    cudaGetSymbolAddress((void**)&act_dev, g_act);

    for (int l = 0; l < L; l++) {
        int use_v = (l > 0);
        init_tmp_kernel<<<gInit, 256>>>(x, use_v, n);
        edge_kernel<<<gEdge, 256>>>(use_v ? (const float*)act_dev : x, ei, E);
        gemm_bn_kernel<<<gGemm, 256>>>(W1, b1, l, 0, n);
        stats_kernel<<<1, D>>>(g1 + (size_t)l * D, be1 + (size_t)l * D, 0, inv_n);
        gemm_bn_kernel<<<gGemm, 256>>>(W2, b2, l, 1, n);
        stats_kernel<<<1, D>>>(g2 + (size_t)l * D, be2 + (size_t)l * D, 1, inv_n);
    }
    finalize_kernel<<<gFin, 256>>>(bi, out, n, K);
}

// round 16
// speedup vs baseline: 1.1186x; 1.1186x over previous
#include <cuda_runtime.h>

#define D 64
#define NMAX 100032
#define EMAX 1600000
#define BM 96

// ---------------- device scratch (no allocations allowed) ----------------
__device__ __align__(16) float g_tmp[NMAX * D];   // act(h) + neighbor sums (GEMM1 input)
__device__ __align__(16) float g_act[NMAX * D];   // read-only act(h) for edge gather
__device__ __align__(16) float g_u[NMAX * D];     // GEMM1 output (pre inner-BN)
__device__ __align__(16) float g_v[NMAX * D];     // GEMM2 output (pre outer-BN)
__device__ __align__(16) int2 g_edge[EMAX];       // packed (src,dst) per edge
__device__ double g_sumA[D], g_sqA[D], g_sumB[D], g_sqB[D];
__device__ __align__(16) float g_scA[D], g_shA[D];   // inner BN scale/shift
__device__ __align__(16) float g_scB[D], g_shB[D];   // outer BN scale/shift

// ---------------- f32x2 helpers ----------------
__device__ __forceinline__ unsigned long long pack2(float x) {
    unsigned long long r;
    asm("mov.b64 %0, {%1, %1};" : "=l"(r) : "r"(__float_as_uint(x)));
    return r;
}
__device__ __forceinline__ void ffma2(unsigned long long& d,
                                      unsigned long long a, unsigned long long b) {
    asm("fma.rn.f32x2 %0, %1, %2, %0;" : "+l"(d) : "l"(a), "l"(b));
}
union Cvt2 { unsigned long long u; float2 f; };

// apply outer-BN(+ReLU) of the previous layer when reading h
__device__ __forceinline__ float4 act_prev(float4 a, int q4, int use_v) {
    if (use_v) {
        float4 s = *(const float4*)&g_scB[q4];
        float4 t = *(const float4*)&g_shB[q4];
        a.x = fmaxf(fmaf(a.x, s.x, t.x), 0.f);
        a.y = fmaxf(fmaf(a.y, s.y, t.y), 0.f);
        a.z = fmaxf(fmaf(a.z, s.z, t.z), 0.f);
        a.w = fmaxf(fmaf(a.w, s.w, t.w), 0.f);
    }
    return a;
}

// ---------------- pack edge list once per call: g_edge[e] = (src, dst) ----------------
__global__ void pack_edges_kernel(const int* __restrict__ ei, int E) {
    int e = blockIdx.x * blockDim.x + threadIdx.x;
    if (e >= E) return;
    g_edge[e] = make_int2(__ldg(&ei[e]), __ldg(&ei[E + e]));
}

// ---------------- tmp = act(h) (+ g_act copy for layers>=1); zero inner-BN accumulators ----------------
__global__ void init_tmp_kernel(const float* __restrict__ x, int use_v, int n) {
    int idx = blockIdx.x * blockDim.x + threadIdx.x;
    if (blockIdx.x == 0 && threadIdx.x < D) {
        g_sumA[threadIdx.x] = 0.0;
        g_sqA[threadIdx.x] = 0.0;
    }
    if (idx >= n * 16) return;
    int q4 = (idx & 15) * 4;
    const float* h = use_v ? g_v : x;
    float4 a = __ldg((const float4*)(h) + idx);
    a = act_prev(a, q4, use_v);
    *((float4*)g_tmp + idx) = a;
    if (use_v) *((float4*)g_act + idx) = a;   // layer 0: edge reads x directly
}

// ---------------- tmp[dst] += act_src[src]; 16 lanes/edge, packed index load ----------------
__global__ void edge_kernel(const float* __restrict__ act_src, int E) {
    int idx = blockIdx.x * blockDim.x + threadIdx.x;
    if (idx >= E * 16) return;
    int e = idx >> 4;
    int q4 = (idx & 15) * 4;
    int2 sd = __ldg(&g_edge[e]);
    float4 a = __ldg((const float4*)(act_src + (size_t)sd.x * D + q4));
    atomicAdd((float4*)(g_tmp + (size_t)sd.y * D + q4), a);
}

// ---------------- fused GEMM + bias + BN-stat accumulation (FFMA2 core, R9 layout) ----------------
// which==0: u = tmp @ W + b,               stats -> sumA/sqA
// which==1: v = relu(bn_inner(u)) @ W + b, stats -> sumB/sqB
__global__ __launch_bounds__(256) void gemm_bn_kernel(
    const float* __restrict__ Wall, const float* __restrict__ ball,
    int l, int which, int n)
{
    __shared__ float As[BM][68];      // padded, float4-aligned
    __shared__ float Ws[D][D];
    __shared__ float red[16][D];

    const float* W = Wall + (size_t)l * D * D;
    const float* bias = ball + (size_t)l * D;
    const float* A = which ? g_u : g_tmp;
    float* out = which ? g_v : g_u;
    double* sum = which ? g_sumB : g_sumA;
    double* sq  = which ? g_sqB  : g_sqA;

    int tid = threadIdx.x;
    int row0 = blockIdx.x * BM;

    // load W tile (64x64)
    #pragma unroll
    for (int i = tid; i < D * D / 4; i += 256)
        ((float4*)Ws)[i] = __ldg((const float4*)W + i);

    // load A tile (BM x 64), applying inner BN + ReLU for GEMM2
    for (int i = tid; i < BM * 16; i += 256) {
        int r = i >> 4, k4 = (i & 15) * 4;
        int gr = row0 + r;
        float4 av = make_float4(0.f, 0.f, 0.f, 0.f);
        if (gr < n) av = __ldg((const float4*)(A + (size_t)gr * D + k4));
        if (which) {
            float4 s = *(const float4*)&g_scA[k4];
            float4 t = *(const float4*)&g_shA[k4];
            av.x = fmaxf(fmaf(av.x, s.x, t.x), 0.f);
            av.y = fmaxf(fmaf(av.y, s.y, t.y), 0.f);
            av.z = fmaxf(fmaf(av.z, s.z, t.z), 0.f);
            av.w = fmaxf(fmaf(av.w, s.w, t.w), 0.f);
        }
        *(float4*)&As[r][k4] = av;
    }
    __syncthreads();

    int tx = tid & 15, ty = tid >> 4;
    int c0 = tx * 4;
    unsigned long long acc01[6], acc23[6];
    #pragma unroll
    for (int i = 0; i < 6; i++) { acc01[i] = 0ull; acc23[i] = 0ull; }

    #pragma unroll
    for (int k = 0; k < D; k += 4) {
        ulonglong2 w0 = *(const ulonglong2*)&Ws[k + 0][c0];
        ulonglong2 w1 = *(const ulonglong2*)&Ws[k + 1][c0];
        ulonglong2 w2 = *(const ulonglong2*)&Ws[k + 2][c0];
        ulonglong2 w3 = *(const ulonglong2*)&Ws[k + 3][c0];
        #pragma unroll
        for (int i = 0; i < 6; i++) {
            float4 a = *(const float4*)&As[ty * 6 + i][k];
            unsigned long long px = pack2(a.x), py = pack2(a.y);
            unsigned long long pz = pack2(a.z), pw = pack2(a.w);
            ffma2(acc01[i], px, w0.x); ffma2(acc23[i], px, w0.y);
            ffma2(acc01[i], py, w1.x); ffma2(acc23[i], py, w1.y);
            ffma2(acc01[i], pz, w2.x); ffma2(acc23[i], pz, w2.y);
            ffma2(acc01[i], pw, w3.x); ffma2(acc23[i], pw, w3.y);
        }
    }

    float4 bv = *(const float4*)(bias + c0);
    float csum[4] = {0.f, 0.f, 0.f, 0.f};
    float csq[4]  = {0.f, 0.f, 0.f, 0.f};
    #pragma unroll
    for (int i = 0; i < 6; i++) {
        int gr = row0 + ty * 6 + i;
        if (gr < n) {
            Cvt2 c01, c23; c01.u = acc01[i]; c23.u = acc23[i];
            float4 o;
            o.x = c01.f.x + bv.x;
            o.y = c01.f.y + bv.y;
            o.z = c23.f.x + bv.z;
            o.w = c23.f.y + bv.w;
            *(float4*)(out + (size_t)gr * D + c0) = o;
            csum[0] += o.x; csq[0] += o.x * o.x;
            csum[1] += o.y; csq[1] += o.y * o.y;
            csum[2] += o.z; csq[2] += o.z * o.z;
            csum[3] += o.w; csq[3] += o.w * o.w;
        }
    }
    __syncthreads();
    #pragma unroll
    for (int c = 0; c < 4; c++) red[ty][c0 + c] = csum[c];
    __syncthreads();
    if (tid < D) {
        float s = 0.f;
        #pragma unroll
        for (int t = 0; t < 16; t++) s += red[t][tid];
        atomicAdd(&sum[tid], (double)s);
    }
    __syncthreads();
    #pragma unroll
    for (int c = 0; c < 4; c++) red[ty][c0 + c] = csq[c];
    __syncthreads();
    if (tid < D) {
        float s = 0.f;
        #pragma unroll
        for (int t = 0; t < 16; t++) s += red[t][tid];
        atomicAdd(&sq[tid], (double)s);
    }
}

// ---------------- finalize BN stats into scale/shift ----------------
__global__ void stats_kernel(const float* __restrict__ gamma,
                             const float* __restrict__ beta,
                             int which, double inv_n) {
    int c = threadIdx.x;
    double s, q;
    if (which == 0) { s = g_sumA[c]; q = g_sqA[c]; }
    else            { s = g_sumB[c]; q = g_sqB[c]; }
    float mean = (float)(s * inv_n);
    float var  = (float)(q * inv_n - (s * inv_n) * (s * inv_n));
    float sc = gamma[c] * rsqrtf(var + 1e-5f);
    float sh = beta[c] - mean * sc;
    if (which == 0) {
        g_scA[c] = sc; g_shA[c] = sh;
        g_sumB[c] = 0.0; g_sqB[c] = 0.0;   // zero outer-BN accumulators for GEMM2
    } else {
        g_scB[c] = sc; g_shB[c] = sh;
    }
}

// ---------------- write node_representation + node_select ----------------
__global__ void finalize_kernel(const int* __restrict__ bi,
                                float* __restrict__ out, int n, int K) {
    int idx = blockIdx.x * blockDim.x + threadIdx.x;
    int total = (n + K) * 16;
    if (idx >= total) return;
    int q4 = (idx & 15) * 4;
    int item = idx >> 4;
    int row;
    size_t opos;
    if (item < n) { row = item; opos = (size_t)item * D + q4; }
    else {
        int k = item - n;
        row = __ldg(&bi[k]);
        opos = (size_t)n * D + (size_t)k * D + q4;
    }
    float4 a = *(const float4*)&g_v[(size_t)row * D + q4];
    float4 s = *(const float4*)&g_scB[q4];
    float4 t = *(const float4*)&g_shB[q4];
    float4 o;
    o.x = fmaf(a.x, s.x, t.x);
    o.y = fmaf(a.y, s.y, t.y);
    o.z = fmaf(a.z, s.z, t.z);
    o.w = fmaf(a.w, s.w, t.w);
    *(float4*)&out[opos] = o;
}

extern "C" void kernel_launch(void* const* d_in, const int* in_sizes, int n_in,
                              void* d_out, int out_size) {
    const float* x   = (const float*)d_in[0];
    const int*   ei  = (const int*)d_in[1];
    const int*   bi  = (const int*)d_in[2];
    const float* W1  = (const float*)d_in[3];
    const float* b1  = (const float*)d_in[4];
    const float* g1  = (const float*)d_in[5];
    const float* be1 = (const float*)d_in[6];
    const float* W2  = (const float*)d_in[7];
    const float* b2  = (const float*)d_in[8];
    const float* g2  = (const float*)d_in[9];
    const float* be2 = (const float*)d_in[10];
    float* out = (float*)d_out;

    int n = in_sizes[0] / D;
    int E = in_sizes[1] / 2;
    int K = in_sizes[2];
    int L = in_sizes[3] / (D * D);

    int gPack = (E + 255) / 256;
    int gInit = (n * 16 + 255) / 256;
    int gEdge = (E * 16 + 255) / 256;
    int gGemm = (n + BM - 1) / BM;
    int gFin  = ((n + K) * 16 + 255) / 256;
    double inv_n = 1.0 / (double)n;

    // device pointer to g_act for the edge kernel on layers >= 1
    float* act_dev = nullptr;
    cudaGetSymbolAddress((void**)&act_dev, g_act);

    pack_edges_kernel<<<gPack, 256>>>(ei, E);

    for (int l = 0; l < L; l++) {
        int use_v = (l > 0);
        init_tmp_kernel<<<gInit, 256>>>(x, use_v, n);
        edge_kernel<<<gEdge, 256>>>(use_v ? (const float*)act_dev : x, E);
        gemm_bn_kernel<<<gGemm, 256>>>(W1, b1, l, 0, n);
        stats_kernel<<<1, D>>>(g1 + (size_t)l * D, be1 + (size_t)l * D, 0, inv_n);
        gemm_bn_kernel<<<gGemm, 256>>>(W2, b2, l, 1, n);
        stats_kernel<<<1, D>>>(g2 + (size_t)l * D, be2 + (size_t)l * D, 1, inv_n);
    }
    finalize_kernel<<<gFin, 256>>>(bi, out, n, K);
}